// round 15
// baseline (speedup 1.0000x reference)
#include <cuda_runtime.h>
#include <cstdint>
#include <cstddef>

#define NROWS 131072
#define NDENSE 13
#define NSPARSE 26
#define NFIELD 39
#define EMBD 16
#define HID 32
#define VOCABSZ 100000
#define EPSV 1e-5f
#define DEPTH 4

// ---- scratch (static device globals; no allocation) ----
__device__ float g_x1[(size_t)NROWS * HID];   // ROW-major [NROWS][HID]
__device__ float g_rest[NROWS];
__device__ float g_R1[(size_t)NSPARSE * VOCABSZ];  // T1 row sums
typedef unsigned long long ull;
__device__ ull   g_Wp[NSPARSE * EMBD * 16];   // (w[e][cp], w[e][cp+16]) pairs
__device__ float g_S1[HID];
__device__ float g_S2[HID * HID];
__device__ float g_u[HID];
__device__ float g_c0;
__device__ int   g_cnt;

// ---- packed f32x2 helpers (Blackwell) ----
__device__ __forceinline__ ull pk2(float a, float b) {
    ull r;
    asm("mov.b64 %0, {%1, %2};" : "=l"(r)
        : "r"(__float_as_uint(a)), "r"(__float_as_uint(b)));
    return r;
}
__device__ __forceinline__ void upk2(ull v, float& a, float& b) {
    unsigned int x, y;
    asm("mov.b64 {%0, %1}, %2;" : "=r"(x), "=r"(y) : "l"(v));
    a = __uint_as_float(x); b = __uint_as_float(y);
}
__device__ __forceinline__ ull fma2(ull a, ull b, ull c) {
    ull d;
    asm("fma.rn.f32x2 %0, %1, %2, %3;" : "=l"(d) : "l"(a), "l"(b), "l"(c));
    return d;
}
__device__ __forceinline__ ull add2(ull a, ull b) {
    ull d;
    asm("add.rn.f32x2 %0, %1, %2;" : "=l"(d) : "l"(a), "l"(b));
    return d;
}
__device__ __forceinline__ ull mul2(ull a, ull b) {
    ull d;
    asm("mul.rn.f32x2 %0, %1, %2;" : "=l"(d) : "l"(a), "l"(b));
    return d;
}
__device__ __forceinline__ ull shflxor2(ull v, int m) {
    unsigned int x = (unsigned int)v, y = (unsigned int)(v >> 32);
    x = __shfl_xor_sync(0xffffffffu, x, m);
    y = __shfl_xor_sync(0xffffffffu, y, m);
    return (ull)x | ((ull)y << 32);
}
__device__ __forceinline__ uint32_t smem_u32(const void* p) {
    uint32_t a;
    asm("{ .reg .u64 t; cvta.to.shared.u64 t, %1; cvt.u32.u64 %0, t; }"
        : "=r"(a) : "l"(p));
    return a;
}
__device__ __forceinline__ void cpasync16(uint32_t dst, const void* src) {
    asm volatile("cp.async.cg.shared.global [%0], [%1], 16;" :: "r"(dst), "l"(src));
}
#define CP_COMMIT() asm volatile("cp.async.commit_group;" ::: "memory")
#define CP_WAIT(n)  asm volatile("cp.async.wait_group %0;" :: "n"(n) : "memory")

// smem word offsets (floats)
#define OFF_RING  0                           // 8 warps * DEPTH * 128 = 4096
#define OFF_ST    (OFF_RING + 8 * DEPTH * 128)
#define OFF_A2P   (OFF_ST + 8 * 160)          // 13*64 packed replicated pairs
#define OFF_B2P   (OFF_A2P + NDENSE * 64)
#define OFF_W2    (OFF_B2P + NDENSE * 64)
#define OFF_BB2   (OFF_W2 + NDENSE * EMBD)
#define OFF_XDT   (OFF_BB2 + NDENSE * EMBD)   // dense xi transposed [13][66]
#define OFF_XVDT  (OFF_XDT + NDENSE * 66)
#define OFF_XST   (OFF_XVDT + NDENSE * 66)    // sparse idx transposed [26][65]
#define OFF_XVST  (OFF_XST + NSPARSE * 65)
#define OFF_W1S   (OFF_XVST + NSPARSE * 65)
#define OFF_B1S   (OFF_W1S + 16)
#define OFF_BIAS  (OFF_B1S + 16)
#define SMEM_WORDS (OFF_BIAS + 64)

// ---- K0a: T1 row-sums (streaming). Quad per row. ----
__global__ __launch_bounds__(256) void rowsum_kernel(const float* __restrict__ T1) {
    int t = blockIdx.x * 256 + threadIdx.x;
    int row = t >> 2, part = t & 3;
    float4 v = __ldcs((const float4*)(T1 + (size_t)row * EMBD + part * 4));
    float s = (v.x + v.y) + (v.z + v.w);
    s += __shfl_xor_sync(0xffffffffu, s, 1);
    s += __shfl_xor_sync(0xffffffffu, s, 2);
    if (part == 0) g_R1[row] = s;
}

// ---- K0b: Wl1 sparse-row pair table ----
__global__ __launch_bounds__(256) void wprep_kernel(const float* __restrict__ Wl1) {
    int i = blockIdx.x * 256 + threadIdx.x;
    if (i < NSPARSE * EMBD * 16) {
        int row = i >> 4, cp = i & 15;
        const float* wr = Wl1 + (size_t)(NDENSE * EMBD + row) * HID;
        g_Wp[i] = pk2(wr[cp], wr[cp + 16]);
    }
}

// ---- K1: fused embed + FM + deep@Wl1 (round-11 body, best measured) ----
__global__ __launch_bounds__(256, 3) void main_kernel(
    const float* __restrict__ Xi_dense, const int* __restrict__ Xi_sparse,
    const float* __restrict__ Xv, const float* __restrict__ bias,
    const float* __restrict__ T2,
    const float* __restrict__ W1d, const float* __restrict__ b1d,
    const float* __restrict__ W2d, const float* __restrict__ b2d,
    const float* __restrict__ Wl1, const float* __restrict__ bl1)
{
    extern __shared__ float sm[];
    float* sst   = sm + OFF_ST;
    float* sA2p  = sm + OFF_A2P;
    float* sB2p  = sm + OFF_B2P;
    float* sW2   = sm + OFF_W2;
    float* sbb2  = sm + OFF_BB2;
    float* sXdT  = sm + OFF_XDT;
    float* sXvDT = sm + OFF_XVDT;
    int*   sXsT  = (int*)(sm + OFF_XST);
    float* sXvST = sm + OFF_XVST;
    float* sw1   = sm + OFF_W1S;
    float* sb1   = sm + OFF_B1S;
    float* sBias = sm + OFF_BIAS;

    const int tid = threadIdx.x;

    for (int i = tid; i < NDENSE * 16; i += 256) {
        int f = i >> 4, cp = i & 15;
        float a0 = 0.f, a1 = 0.f, b0 = 0.f, b1 = 0.f;
        #pragma unroll
        for (int e = 0; e < EMBD; e++) {
            float w0 = Wl1[(f * EMBD + e) * HID + cp];
            float w1 = Wl1[(f * EMBD + e) * HID + cp + 16];
            float ww = W2d[f * EMBD + e], bb = b2d[f * EMBD + e];
            a0 = fmaf(ww, w0, a0); a1 = fmaf(ww, w1, a1);
            b0 = fmaf(bb, w0, b0); b1 = fmaf(bb, w1, b1);
        }
        sA2p[f * 64 + cp * 4 + 0] = a0; sA2p[f * 64 + cp * 4 + 1] = a0;
        sA2p[f * 64 + cp * 4 + 2] = a1; sA2p[f * 64 + cp * 4 + 3] = a1;
        sB2p[f * 64 + cp * 4 + 0] = b0; sB2p[f * 64 + cp * 4 + 1] = b0;
        sB2p[f * 64 + cp * 4 + 2] = b1; sB2p[f * 64 + cp * 4 + 3] = b1;
    }
    if (tid < NDENSE * EMBD) {
        sW2[tid]  = W2d[tid];
        sbb2[tid] = b2d[tid];
    }
    if (tid < NDENSE) {
        float a = 0.f, b = 0.f;
        #pragma unroll
        for (int e = 0; e < EMBD; e++) {
            a += W1d[tid * EMBD + e];
            b += b1d[tid * EMBD + e];
        }
        sw1[tid] = a; sb1[tid] = b;
    }
    if (blockIdx.x == 0) {
        if (tid < HID) g_S1[tid] = 0.f;
        for (int i = tid; i < HID * HID; i += 256) g_S2[i] = 0.f;
        if (tid == 0) g_cnt = 0;
    }

    const int warp = tid >> 5;
    const int lane = tid & 31;
    const int q    = lane >> 2;
    const int ql   = lane & 3;
    const int rh   = lane >> 4;
    const int cp   = lane & 15;
    const int w8   = warp * 8;
    const int w8q  = w8 + q;
    const float blj = __ldg(bl1 + lane);
    const ull blp = pk2(blj, blj);
    const ull* wlane = g_Wp + rh * 16 + cp;
    float* stw = sst + warp * 160;
    const uint32_t ringb = smem_u32(sm) + (uint32_t)(OFF_RING + warp * (DEPTH * 128)) * 4u;
    const uint32_t laneoff = (uint32_t)(q * 4 + ql) * 16u;
    const float* ringw = sm + OFF_RING + warp * (DEPTH * 128);

    #pragma unroll 1
    for (int g = 0; g < 2; g++) {
        const int base = blockIdx.x * 128 + g * 64;
        __syncthreads();
        for (int i = tid; i < 64 * NSPARSE; i += 256) {
            int r = i / NSPARSE, f = i % NSPARSE;
            sXsT[f * 65 + r] = Xi_sparse[(size_t)base * NSPARSE + i];
        }
        for (int i = tid; i < 64 * NFIELD; i += 256) {
            int r = i / NFIELD, f = i % NFIELD;
            float val = Xv[(size_t)base * NFIELD + i];
            if (f < NDENSE) sXvDT[f * 66 + r] = val;
            else            sXvST[(f - NDENSE) * 65 + r] = val;
        }
        for (int i = tid; i < 64 * NDENSE; i += 256) {
            int r = i / NDENSE, f = i % NDENSE;
            sXdT[f * 66 + r] = Xi_dense[(size_t)base * NDENSE + i];
        }
        if (tid < 64) sBias[tid] = bias[base + tid];
        __syncthreads();

        ull x1p[8];
        #pragma unroll
        for (int i = 0; i < 8; i++) x1p[i] = 0ull;
        ull s01 = 0ull, s23 = 0ull, sqp = 0ull;
        float rest = (ql == 0) ? sBias[w8q] : 0.f;

        #pragma unroll
        for (int f = 0; f < NDENSE; f++) {
            float xi = sXdT[f * 66 + w8q];
            float v  = sXvDT[f * 66 + w8q];
            if (ql == 0) rest = fmaf(v, fmaf(xi, sw1[f], sb1[f]), rest);
            float4 w2 = *(const float4*)(sW2 + f * EMBD + ql * 4);
            float4 c2 = *(const float4*)(sbb2 + f * EMBD + ql * 4);
            float t0 = fmaf(xi, w2.x, c2.x) * v;
            float t1 = fmaf(xi, w2.y, c2.y) * v;
            float t2 = fmaf(xi, w2.z, c2.z) * v;
            float t3 = fmaf(xi, w2.w, c2.w) * v;
            ull p01 = pk2(t0, t1), p23 = pk2(t2, t3);
            s01 = add2(s01, p01); s23 = add2(s23, p23);
            sqp = fma2(p01, p01, sqp); sqp = fma2(p23, p23, sqp);
            if ((f & 1) == rh) {
                ulonglong2 ap = *(const ulonglong2*)(sA2p + f * 64 + cp * 4);
                ulonglong2 bp = *(const ulonglong2*)(sB2p + f * 64 + cp * 4);
                #pragma unroll
                for (int r = 0; r < 4; r++) {
                    ull xi2 = *(const ull*)(sXdT + f * 66 + w8 + 2 * r);
                    ull v2  = *(const ull*)(sXvDT + f * 66 + w8 + 2 * r);
                    ull xiv2 = mul2(xi2, v2);
                    x1p[r]     = fma2(xiv2, ap.x, x1p[r]);
                    x1p[r]     = fma2(v2,   bp.x, x1p[r]);
                    x1p[4 + r] = fma2(xiv2, ap.y, x1p[4 + r]);
                    x1p[4 + r] = fma2(v2,   bp.y, x1p[4 + r]);
                }
            }
        }

        #pragma unroll
        for (int pf = 0; pf < DEPTH; pf++) {
            int id = sXsT[pf * 65 + w8 + q];
            const float* src = T2 + ((size_t)pf * VOCABSZ + (size_t)id) * EMBD + ql * 4;
            cpasync16(ringb + (uint32_t)(pf & (DEPTH - 1)) * 512u + laneoff, src);
            CP_COMMIT();
        }
        float rs0 = __ldcg(g_R1 + sXsT[w8q]);
        float rs1 = __ldcg(g_R1 + VOCABSZ + sXsT[65 + w8q]);

        #pragma unroll 1
        for (int f = 0; f < NSPARSE; f++) {
            CP_WAIT(DEPTH - 1);
            float4 cb = *(const float4*)(ringw + (f & (DEPTH - 1)) * 128 + (q * 4 + ql) * 4);
            float cv = sXvST[f * 65 + w8q];
            if (ql == 0) rest = fmaf(cv, rs0, rest);
            rs0 = rs1;
            if (f + 2 < NSPARSE)
                rs1 = __ldcg(g_R1 + (size_t)(f + 2) * VOCABSZ + sXsT[(f + 2) * 65 + w8q]);

            float t0 = cb.x * cv, t1 = cb.y * cv, t2 = cb.z * cv, t3 = cb.w * cv;
            ull p01 = pk2(t0, t1), p23 = pk2(t2, t3);
            s01 = add2(s01, p01); s23 = add2(s23, p23);
            sqp = fma2(p01, p01, sqp); sqp = fma2(p23, p23, sqp);

            stw[(2 * ql + 0) * 20 + 0 + q] = t0;
            stw[(2 * ql + 0) * 20 + 8 + q] = t1;
            stw[(2 * ql + 1) * 20 + 0 + q] = t2;
            stw[(2 * ql + 1) * 20 + 8 + q] = t3;
            __syncwarp();

            #pragma unroll
            for (int p = 0; p < 8; p++) {
                ull wp = __ldg(wlane + (f * 16 + 2 * p) * 16);
                float wlo, whi; upk2(wp, wlo, whi);
                ull w0 = pk2(wlo, wlo), w1 = pk2(whi, whi);
                const ulonglong2* tp = (const ulonglong2*)(stw + p * 20 + rh * 8);
                ulonglong2 ta = tp[0];
                ulonglong2 tb = tp[1];
                x1p[0] = fma2(ta.x, w0, x1p[0]);
                x1p[1] = fma2(ta.y, w0, x1p[1]);
                x1p[2] = fma2(tb.x, w0, x1p[2]);
                x1p[3] = fma2(tb.y, w0, x1p[3]);
                x1p[4] = fma2(ta.x, w1, x1p[4]);
                x1p[5] = fma2(ta.y, w1, x1p[5]);
                x1p[6] = fma2(tb.x, w1, x1p[6]);
                x1p[7] = fma2(tb.y, w1, x1p[7]);
            }
            __syncwarp();

            {
                int pf = f + DEPTH;
                if (pf < NSPARSE) {
                    int id = sXsT[pf * 65 + w8 + q];
                    const float* src = T2 + ((size_t)pf * VOCABSZ + (size_t)id) * EMBD + ql * 4;
                    cpasync16(ringb + (uint32_t)(pf & (DEPTH - 1)) * 512u + laneoff, src);
                }
                CP_COMMIT();
            }
        }

        {
            ull f2 = fma2(s01, s01, 0ull);
            f2 = fma2(s23, s23, f2);
            float flo, fhi; upk2(f2, flo, fhi);
            float qlo, qhi; upk2(sqp, qlo, qhi);
            rest += 0.5f * ((flo + fhi) - (qlo + qhi));
        }
        rest += __shfl_xor_sync(0xffffffffu, rest, 1);
        rest += __shfl_xor_sync(0xffffffffu, rest, 2);
        if (ql == 0) g_rest[base + w8q] = rest;

        #pragma unroll
        for (int i = 0; i < 8; i++)
            x1p[i] = add2(x1p[i], shflxor2(x1p[i], 16));
        #pragma unroll
        for (int r = 0; r < 4; r++) {
            ull v = add2((rh == 0) ? x1p[r] : x1p[4 + r], blp);
            float lo, hi; upk2(v, lo, hi);
            g_x1[(size_t)(base + w8 + 2 * r)     * HID + lane] = lo;
            g_x1[(size_t)(base + w8 + 2 * r + 1) * HID + lane] = hi;
        }
    }
}

// ---- K2: register-tiled syrk S1/S2; last block folds BN -> u, c0 ----
// 64-thread group: thread (ki,li) owns 4x4 tile S2[4ki..][4li..]. Per row:
// two LDG.128 within one 128B line (broadcast-coalesced) + 8 fma2. No shfl,
// no smem in the hot loop.
__global__ __launch_bounds__(256) void stats_kernel(
        const float* __restrict__ g1, const float* __restrict__ be1,
        const float* __restrict__ Wl2, const float* __restrict__ bl2,
        const float* __restrict__ g2, const float* __restrict__ be2) {
    __shared__ float sred[4 * 1024];
    __shared__ float s1red[4 * 32];
    __shared__ int isLast;
    const int t = threadIdx.x;
    const int grp = t >> 6;
    const int t6 = t & 63;
    const int ki = t6 >> 3, li = t6 & 7;
    const int g = blockIdx.x * 4 + grp;          // 512 groups, 256 rows each
    const float* base = g_x1 + (size_t)g * 256 * HID;

    ull acc[8];                                   // [i*2+j]: k=4ki+i, l-pair j
    #pragma unroll
    for (int i = 0; i < 8; i++) acc[i] = 0ull;
    float s1v[4] = {0.f, 0.f, 0.f, 0.f};

    #pragma unroll 1
    for (int r = 0; r < 256; r += 2) {
        float4 a0 = __ldcg((const float4*)(base + (size_t)r * HID + 4 * ki));
        float4 b0 = __ldcg((const float4*)(base + (size_t)r * HID + 4 * li));
        float4 a1 = __ldcg((const float4*)(base + (size_t)(r + 1) * HID + 4 * ki));
        float4 b1 = __ldcg((const float4*)(base + (size_t)(r + 1) * HID + 4 * li));
        ull b001 = pk2(b0.x, b0.y), b023 = pk2(b0.z, b0.w);
        ull b101 = pk2(b1.x, b1.y), b123 = pk2(b1.z, b1.w);
        ull ax0 = pk2(a0.x, a0.x), ay0 = pk2(a0.y, a0.y);
        ull az0 = pk2(a0.z, a0.z), aw0 = pk2(a0.w, a0.w);
        ull ax1 = pk2(a1.x, a1.x), ay1 = pk2(a1.y, a1.y);
        ull az1 = pk2(a1.z, a1.z), aw1 = pk2(a1.w, a1.w);
        acc[0] = fma2(ax0, b001, acc[0]); acc[1] = fma2(ax0, b023, acc[1]);
        acc[2] = fma2(ay0, b001, acc[2]); acc[3] = fma2(ay0, b023, acc[3]);
        acc[4] = fma2(az0, b001, acc[4]); acc[5] = fma2(az0, b023, acc[5]);
        acc[6] = fma2(aw0, b001, acc[6]); acc[7] = fma2(aw0, b023, acc[7]);
        acc[0] = fma2(ax1, b101, acc[0]); acc[1] = fma2(ax1, b123, acc[1]);
        acc[2] = fma2(ay1, b101, acc[2]); acc[3] = fma2(ay1, b123, acc[3]);
        acc[4] = fma2(az1, b101, acc[4]); acc[5] = fma2(az1, b123, acc[5]);
        acc[6] = fma2(aw1, b101, acc[6]); acc[7] = fma2(aw1, b123, acc[7]);
        if (li == 0) {
            s1v[0] += a0.x + a1.x;
            s1v[1] += a0.y + a1.y;
            s1v[2] += a0.z + a1.z;
            s1v[3] += a0.w + a1.w;
        }
    }

    // stage group results, sum across the 4 groups, one atomic per element
    #pragma unroll
    for (int i = 0; i < 4; i++) {
        #pragma unroll
        for (int j = 0; j < 2; j++) {
            float lo, hi; upk2(acc[i * 2 + j], lo, hi);
            sred[grp * 1024 + (4 * ki + i) * 32 + 4 * li + 2 * j]     = lo;
            sred[grp * 1024 + (4 * ki + i) * 32 + 4 * li + 2 * j + 1] = hi;
        }
    }
    if (li == 0) {
        #pragma unroll
        for (int i = 0; i < 4; i++) s1red[grp * 32 + 4 * ki + i] = s1v[i];
    }
    __syncthreads();
    for (int i = t; i < 1024; i += 256) {
        float s = (sred[i] + sred[1024 + i]) + (sred[2048 + i] + sred[3072 + i]);
        atomicAdd(&g_S2[i], s);
    }
    if (t < 32) {
        float s = (s1red[t] + s1red[32 + t]) + (s1red[64 + t] + s1red[96 + t]);
        atomicAdd(&g_S1[t], s);
    }
    __syncthreads();

    if (t == 0) {
        __threadfence();
        int old = atomicAdd(&g_cnt, 1);
        isLast = (old == (int)gridDim.x - 1) ? 1 : 0;
    }
    __syncthreads();
    if (!isLast) return;

    // ---- closed-form BN fold (256 threads; overlays sred) ----
    float* m1s = sred;            // 32
    float* a1s = sred + 32;       // 32
    float* a2s = sred + 64;       // 32
    float* qv  = sred + 96;       // 32*33
    float* Cm  = qv + 1056;       // 32*33
    float* part = Cm + 1056;      // 32*33
    const int j  = t & 31;
    const int kw = t >> 5;        // 0..7
    const float invN = 1.f / (float)NROWS;

    if (kw == 0) {
        float m1 = __ldcg(&g_S1[j]) * invN;
        float v1 = __ldcg(&g_S2[j * HID + j]) * invN - m1 * m1;
        m1s[j] = m1;
        a1s[j] = g1[j] * rsqrtf(v1 + EPSV);
    }
    __syncthreads();
    #pragma unroll
    for (int c = 0; c < 4; c++) {
        int kk = c * 8 + kw;
        Cm[kk * 33 + j] = __ldcg(&g_S2[kk * HID + j]) * invN - m1s[kk] * m1s[j];
        qv[kk * 33 + j] = a1s[kk] * Wl2[kk * HID + j];
    }
    __syncthreads();
    #pragma unroll
    for (int c = 0; c < 4; c++) {
        int kk = c * 8 + kw;
        float accv = 0.f;
        #pragma unroll 8
        for (int ll = 0; ll < HID; ll++) accv = fmaf(qv[ll * 33 + j], Cm[kk * 33 + ll], accv);
        part[kk * 33 + j] = qv[kk * 33 + j] * accv;
    }
    __syncthreads();

    if (kw == 0) {
        float vy = 0.f;
        #pragma unroll
        for (int m = 0; m < HID; m++) vy += part[m * 33 + j];
        float my = bl2[j];
        #pragma unroll
        for (int m = 0; m < HID; m++) my = fmaf(be1[m], Wl2[m * HID + j], my);
        float a2 = g2[j] * rsqrtf(vy + EPSV);
        a2s[j] = a2;
        float cpart = fmaf(a2, bl2[j] - my, be2[j]);
        __syncwarp();
        float wt = 0.f;
        #pragma unroll
        for (int jj = 0; jj < HID; jj++) wt = fmaf(Wl2[j * HID + jj], a2s[jj], wt);
        g_u[j] = a1s[j] * wt;
        cpart = fmaf(be1[j] - a1s[j] * m1s[j], wt, cpart);
        #pragma unroll
        for (int off = 16; off > 0; off >>= 1) cpart += __shfl_down_sync(0xffffffffu, cpart, off);
        if (j == 0) g_c0 = cpart;
    }
}

// ---- K3: out = rest + x1 . u + c0 (row-major x1 via smem tile) ----
__global__ __launch_bounds__(256) void out_kernel(float* __restrict__ out) {
    __shared__ float s[256 * 33];
    __shared__ float us[HID];
    __shared__ float c0s;
    const int t = threadIdx.x;
    const int base = blockIdx.x * 256;
    #pragma unroll
    for (int si = 0; si < 32; si++) {
        int i = t + si * 256;
        int r = i >> 5, jj = i & 31;
        s[r * 33 + jj] = g_x1[(size_t)base * HID + i];
    }
    if (t < HID) us[t] = g_u[t];
    if (t == HID) c0s = g_c0;
    __syncthreads();
    float acc = g_rest[base + t] + c0s;
    #pragma unroll 8
    for (int jj = 0; jj < HID; jj++)
        acc = fmaf(s[t * 33 + jj], us[jj], acc);
    out[base + t] = acc;
}

extern "C" void kernel_launch(void* const* d_in, const int* in_sizes, int n_in,
                              void* d_out, int out_size) {
    const float* Xi_dense  = (const float*)d_in[0];
    const int*   Xi_sparse = (const int*)d_in[1];
    const float* Xv   = (const float*)d_in[2];
    const float* bias = (const float*)d_in[3];
    const float* W1d  = (const float*)d_in[4];
    const float* b1d  = (const float*)d_in[5];
    const float* T1   = (const float*)d_in[6];
    const float* W2d  = (const float*)d_in[7];
    const float* b2d  = (const float*)d_in[8];
    const float* T2   = (const float*)d_in[9];
    const float* Wl1  = (const float*)d_in[10];
    const float* bl1  = (const float*)d_in[11];
    const float* g1   = (const float*)d_in[12];
    const float* be1  = (const float*)d_in[13];
    const float* Wl2  = (const float*)d_in[14];
    const float* bl2  = (const float*)d_in[15];
    const float* g2   = (const float*)d_in[16];
    const float* be2  = (const float*)d_in[17];
    float* out = (float*)d_out;

    size_t smem = (size_t)SMEM_WORDS * sizeof(float);
    cudaFuncSetAttribute(main_kernel, cudaFuncAttributeMaxDynamicSharedMemorySize, (int)smem);

    wprep_kernel<<<(NSPARSE * EMBD * 16 + 255) / 256, 256>>>(Wl1);
    rowsum_kernel<<<(NSPARSE * VOCABSZ * 4) / 256, 256>>>(T1);
    main_kernel<<<NROWS / 128, 256, smem>>>(Xi_dense, Xi_sparse, Xv, bias,
                                            T2, W1d, b1d, W2d, b2d, Wl1, bl1);
    stats_kernel<<<128, 256>>>(g1, be1, Wl2, bl2, g2, be2);
    out_kernel<<<NROWS / 256, 256>>>(out);
}

// round 16
// speedup vs baseline: 1.3565x; 1.3565x over previous
#include <cuda_runtime.h>
#include <cstdint>
#include <cstddef>

#define NROWS 131072
#define NDENSE 13
#define NSPARSE 26
#define NFIELD 39
#define EMBD 16
#define HID 32
#define VOCABSZ 100000
#define EPSV 1e-5f
#define DEPTH 4

// ---- scratch (static device globals; no allocation) ----
__device__ float g_x1[(size_t)NROWS * HID];   // ROW-major [NROWS][HID]
__device__ float g_rest[NROWS];
__device__ float g_R1[(size_t)NSPARSE * VOCABSZ];  // T1 row sums
typedef unsigned long long ull;
__device__ ull   g_Wp[NSPARSE * EMBD * 16];   // (w[e][cp], w[e][cp+16]) pairs
__device__ float g_S1[HID];
__device__ float g_S2[HID * HID];
__device__ float g_u[HID];
__device__ float g_c0;
__device__ int   g_cnt;

// ---- packed f32x2 helpers (Blackwell) ----
__device__ __forceinline__ ull pk2(float a, float b) {
    ull r;
    asm("mov.b64 %0, {%1, %2};" : "=l"(r)
        : "r"(__float_as_uint(a)), "r"(__float_as_uint(b)));
    return r;
}
__device__ __forceinline__ void upk2(ull v, float& a, float& b) {
    unsigned int x, y;
    asm("mov.b64 {%0, %1}, %2;" : "=r"(x), "=r"(y) : "l"(v));
    a = __uint_as_float(x); b = __uint_as_float(y);
}
__device__ __forceinline__ ull fma2(ull a, ull b, ull c) {
    ull d;
    asm("fma.rn.f32x2 %0, %1, %2, %3;" : "=l"(d) : "l"(a), "l"(b), "l"(c));
    return d;
}
__device__ __forceinline__ ull add2(ull a, ull b) {
    ull d;
    asm("add.rn.f32x2 %0, %1, %2;" : "=l"(d) : "l"(a), "l"(b));
    return d;
}
__device__ __forceinline__ ull mul2(ull a, ull b) {
    ull d;
    asm("mul.rn.f32x2 %0, %1, %2;" : "=l"(d) : "l"(a), "l"(b));
    return d;
}
__device__ __forceinline__ ull shflxor2(ull v, int m) {
    unsigned int x = (unsigned int)v, y = (unsigned int)(v >> 32);
    x = __shfl_xor_sync(0xffffffffu, x, m);
    y = __shfl_xor_sync(0xffffffffu, y, m);
    return (ull)x | ((ull)y << 32);
}
__device__ __forceinline__ uint32_t smem_u32(const void* p) {
    uint32_t a;
    asm("{ .reg .u64 t; cvta.to.shared.u64 t, %1; cvt.u32.u64 %0, t; }"
        : "=r"(a) : "l"(p));
    return a;
}
__device__ __forceinline__ void cpasync16(uint32_t dst, const void* src) {
    asm volatile("cp.async.cg.shared.global [%0], [%1], 16;" :: "r"(dst), "l"(src));
}
#define CP_COMMIT() asm volatile("cp.async.commit_group;" ::: "memory")
#define CP_WAIT(n)  asm volatile("cp.async.wait_group %0;" :: "n"(n) : "memory")

// smem word offsets (floats)
#define OFF_RING  0                           // 8 warps * DEPTH * 128 = 4096
#define OFF_ST    (OFF_RING + 8 * DEPTH * 128)
#define OFF_A2P   (OFF_ST + 8 * 160)          // 13*64 packed replicated pairs
#define OFF_B2P   (OFF_A2P + NDENSE * 64)
#define OFF_W2    (OFF_B2P + NDENSE * 64)
#define OFF_BB2   (OFF_W2 + NDENSE * EMBD)
#define OFF_XDT   (OFF_BB2 + NDENSE * EMBD)   // dense xi transposed [13][66]
#define OFF_XVDT  (OFF_XDT + NDENSE * 66)
#define OFF_XST   (OFF_XVDT + NDENSE * 66)    // sparse idx transposed [26][65]
#define OFF_XVST  (OFF_XST + NSPARSE * 65)
#define OFF_W1S   (OFF_XVST + NSPARSE * 65)
#define OFF_B1S   (OFF_W1S + 16)
#define OFF_BIAS  (OFF_B1S + 16)
#define SMEM_WORDS (OFF_BIAS + 64)

// ---- K0a: T1 row-sums (streaming). Quad per row. ----
__global__ __launch_bounds__(256) void rowsum_kernel(const float* __restrict__ T1) {
    int t = blockIdx.x * 256 + threadIdx.x;
    int row = t >> 2, part = t & 3;
    float4 v = __ldcs((const float4*)(T1 + (size_t)row * EMBD + part * 4));
    float s = (v.x + v.y) + (v.z + v.w);
    s += __shfl_xor_sync(0xffffffffu, s, 1);
    s += __shfl_xor_sync(0xffffffffu, s, 2);
    if (part == 0) g_R1[row] = s;
}

// ---- K0b: Wl1 sparse-row pair table ----
__global__ __launch_bounds__(256) void wprep_kernel(const float* __restrict__ Wl1) {
    int i = blockIdx.x * 256 + threadIdx.x;
    if (i < NSPARSE * EMBD * 16) {
        int row = i >> 4, cp = i & 15;
        const float* wr = Wl1 + (size_t)(NDENSE * EMBD + row) * HID;
        g_Wp[i] = pk2(wr[cp], wr[cp + 16]);
    }
}

// ---- K1: fused embed + FM + deep@Wl1 (round-11 body, best measured) ----
__global__ __launch_bounds__(256, 3) void main_kernel(
    const float* __restrict__ Xi_dense, const int* __restrict__ Xi_sparse,
    const float* __restrict__ Xv, const float* __restrict__ bias,
    const float* __restrict__ T2,
    const float* __restrict__ W1d, const float* __restrict__ b1d,
    const float* __restrict__ W2d, const float* __restrict__ b2d,
    const float* __restrict__ Wl1, const float* __restrict__ bl1)
{
    extern __shared__ float sm[];
    float* sst   = sm + OFF_ST;
    float* sA2p  = sm + OFF_A2P;
    float* sB2p  = sm + OFF_B2P;
    float* sW2   = sm + OFF_W2;
    float* sbb2  = sm + OFF_BB2;
    float* sXdT  = sm + OFF_XDT;
    float* sXvDT = sm + OFF_XVDT;
    int*   sXsT  = (int*)(sm + OFF_XST);
    float* sXvST = sm + OFF_XVST;
    float* sw1   = sm + OFF_W1S;
    float* sb1   = sm + OFF_B1S;
    float* sBias = sm + OFF_BIAS;

    const int tid = threadIdx.x;

    for (int i = tid; i < NDENSE * 16; i += 256) {
        int f = i >> 4, cp = i & 15;
        float a0 = 0.f, a1 = 0.f, b0 = 0.f, b1 = 0.f;
        #pragma unroll
        for (int e = 0; e < EMBD; e++) {
            float w0 = Wl1[(f * EMBD + e) * HID + cp];
            float w1 = Wl1[(f * EMBD + e) * HID + cp + 16];
            float ww = W2d[f * EMBD + e], bb = b2d[f * EMBD + e];
            a0 = fmaf(ww, w0, a0); a1 = fmaf(ww, w1, a1);
            b0 = fmaf(bb, w0, b0); b1 = fmaf(bb, w1, b1);
        }
        sA2p[f * 64 + cp * 4 + 0] = a0; sA2p[f * 64 + cp * 4 + 1] = a0;
        sA2p[f * 64 + cp * 4 + 2] = a1; sA2p[f * 64 + cp * 4 + 3] = a1;
        sB2p[f * 64 + cp * 4 + 0] = b0; sB2p[f * 64 + cp * 4 + 1] = b0;
        sB2p[f * 64 + cp * 4 + 2] = b1; sB2p[f * 64 + cp * 4 + 3] = b1;
    }
    if (tid < NDENSE * EMBD) {
        sW2[tid]  = W2d[tid];
        sbb2[tid] = b2d[tid];
    }
    if (tid < NDENSE) {
        float a = 0.f, b = 0.f;
        #pragma unroll
        for (int e = 0; e < EMBD; e++) {
            a += W1d[tid * EMBD + e];
            b += b1d[tid * EMBD + e];
        }
        sw1[tid] = a; sb1[tid] = b;
    }
    if (blockIdx.x == 0) {
        if (tid < HID) g_S1[tid] = 0.f;
        for (int i = tid; i < HID * HID; i += 256) g_S2[i] = 0.f;
        if (tid == 0) g_cnt = 0;
    }

    const int warp = tid >> 5;
    const int lane = tid & 31;
    const int q    = lane >> 2;
    const int ql   = lane & 3;
    const int rh   = lane >> 4;
    const int cp   = lane & 15;
    const int w8   = warp * 8;
    const int w8q  = w8 + q;
    const float blj = __ldg(bl1 + lane);
    const ull blp = pk2(blj, blj);
    const ull* wlane = g_Wp + rh * 16 + cp;
    float* stw = sst + warp * 160;
    const uint32_t ringb = smem_u32(sm) + (uint32_t)(OFF_RING + warp * (DEPTH * 128)) * 4u;
    const uint32_t laneoff = (uint32_t)(q * 4 + ql) * 16u;
    const float* ringw = sm + OFF_RING + warp * (DEPTH * 128);

    #pragma unroll 1
    for (int g = 0; g < 2; g++) {
        const int base = blockIdx.x * 128 + g * 64;
        __syncthreads();
        for (int i = tid; i < 64 * NSPARSE; i += 256) {
            int r = i / NSPARSE, f = i % NSPARSE;
            sXsT[f * 65 + r] = Xi_sparse[(size_t)base * NSPARSE + i];
        }
        for (int i = tid; i < 64 * NFIELD; i += 256) {
            int r = i / NFIELD, f = i % NFIELD;
            float val = Xv[(size_t)base * NFIELD + i];
            if (f < NDENSE) sXvDT[f * 66 + r] = val;
            else            sXvST[(f - NDENSE) * 65 + r] = val;
        }
        for (int i = tid; i < 64 * NDENSE; i += 256) {
            int r = i / NDENSE, f = i % NDENSE;
            sXdT[f * 66 + r] = Xi_dense[(size_t)base * NDENSE + i];
        }
        if (tid < 64) sBias[tid] = bias[base + tid];
        __syncthreads();

        ull x1p[8];
        #pragma unroll
        for (int i = 0; i < 8; i++) x1p[i] = 0ull;
        ull s01 = 0ull, s23 = 0ull, sqp = 0ull;
        float rest = (ql == 0) ? sBias[w8q] : 0.f;

        #pragma unroll
        for (int f = 0; f < NDENSE; f++) {
            float xi = sXdT[f * 66 + w8q];
            float v  = sXvDT[f * 66 + w8q];
            if (ql == 0) rest = fmaf(v, fmaf(xi, sw1[f], sb1[f]), rest);
            float4 w2 = *(const float4*)(sW2 + f * EMBD + ql * 4);
            float4 c2 = *(const float4*)(sbb2 + f * EMBD + ql * 4);
            float t0 = fmaf(xi, w2.x, c2.x) * v;
            float t1 = fmaf(xi, w2.y, c2.y) * v;
            float t2 = fmaf(xi, w2.z, c2.z) * v;
            float t3 = fmaf(xi, w2.w, c2.w) * v;
            ull p01 = pk2(t0, t1), p23 = pk2(t2, t3);
            s01 = add2(s01, p01); s23 = add2(s23, p23);
            sqp = fma2(p01, p01, sqp); sqp = fma2(p23, p23, sqp);
            if ((f & 1) == rh) {
                ulonglong2 ap = *(const ulonglong2*)(sA2p + f * 64 + cp * 4);
                ulonglong2 bp = *(const ulonglong2*)(sB2p + f * 64 + cp * 4);
                #pragma unroll
                for (int r = 0; r < 4; r++) {
                    ull xi2 = *(const ull*)(sXdT + f * 66 + w8 + 2 * r);
                    ull v2  = *(const ull*)(sXvDT + f * 66 + w8 + 2 * r);
                    ull xiv2 = mul2(xi2, v2);
                    x1p[r]     = fma2(xiv2, ap.x, x1p[r]);
                    x1p[r]     = fma2(v2,   bp.x, x1p[r]);
                    x1p[4 + r] = fma2(xiv2, ap.y, x1p[4 + r]);
                    x1p[4 + r] = fma2(v2,   bp.y, x1p[4 + r]);
                }
            }
        }

        #pragma unroll
        for (int pf = 0; pf < DEPTH; pf++) {
            int id = sXsT[pf * 65 + w8 + q];
            const float* src = T2 + ((size_t)pf * VOCABSZ + (size_t)id) * EMBD + ql * 4;
            cpasync16(ringb + (uint32_t)(pf & (DEPTH - 1)) * 512u + laneoff, src);
            CP_COMMIT();
        }
        float rs0 = __ldcg(g_R1 + sXsT[w8q]);
        float rs1 = __ldcg(g_R1 + VOCABSZ + sXsT[65 + w8q]);

        #pragma unroll 1
        for (int f = 0; f < NSPARSE; f++) {
            CP_WAIT(DEPTH - 1);
            float4 cb = *(const float4*)(ringw + (f & (DEPTH - 1)) * 128 + (q * 4 + ql) * 4);
            float cv = sXvST[f * 65 + w8q];
            if (ql == 0) rest = fmaf(cv, rs0, rest);
            rs0 = rs1;
            if (f + 2 < NSPARSE)
                rs1 = __ldcg(g_R1 + (size_t)(f + 2) * VOCABSZ + sXsT[(f + 2) * 65 + w8q]);

            float t0 = cb.x * cv, t1 = cb.y * cv, t2 = cb.z * cv, t3 = cb.w * cv;
            ull p01 = pk2(t0, t1), p23 = pk2(t2, t3);
            s01 = add2(s01, p01); s23 = add2(s23, p23);
            sqp = fma2(p01, p01, sqp); sqp = fma2(p23, p23, sqp);

            stw[(2 * ql + 0) * 20 + 0 + q] = t0;
            stw[(2 * ql + 0) * 20 + 8 + q] = t1;
            stw[(2 * ql + 1) * 20 + 0 + q] = t2;
            stw[(2 * ql + 1) * 20 + 8 + q] = t3;
            __syncwarp();

            #pragma unroll
            for (int p = 0; p < 8; p++) {
                ull wp = __ldg(wlane + (f * 16 + 2 * p) * 16);
                float wlo, whi; upk2(wp, wlo, whi);
                ull w0 = pk2(wlo, wlo), w1 = pk2(whi, whi);
                const ulonglong2* tp = (const ulonglong2*)(stw + p * 20 + rh * 8);
                ulonglong2 ta = tp[0];
                ulonglong2 tb = tp[1];
                x1p[0] = fma2(ta.x, w0, x1p[0]);
                x1p[1] = fma2(ta.y, w0, x1p[1]);
                x1p[2] = fma2(tb.x, w0, x1p[2]);
                x1p[3] = fma2(tb.y, w0, x1p[3]);
                x1p[4] = fma2(ta.x, w1, x1p[4]);
                x1p[5] = fma2(ta.y, w1, x1p[5]);
                x1p[6] = fma2(tb.x, w1, x1p[6]);
                x1p[7] = fma2(tb.y, w1, x1p[7]);
            }
            __syncwarp();

            {
                int pf = f + DEPTH;
                if (pf < NSPARSE) {
                    int id = sXsT[pf * 65 + w8 + q];
                    const float* src = T2 + ((size_t)pf * VOCABSZ + (size_t)id) * EMBD + ql * 4;
                    cpasync16(ringb + (uint32_t)(pf & (DEPTH - 1)) * 512u + laneoff, src);
                }
                CP_COMMIT();
            }
        }

        {
            ull f2 = fma2(s01, s01, 0ull);
            f2 = fma2(s23, s23, f2);
            float flo, fhi; upk2(f2, flo, fhi);
            float qlo, qhi; upk2(sqp, qlo, qhi);
            rest += 0.5f * ((flo + fhi) - (qlo + qhi));
        }
        rest += __shfl_xor_sync(0xffffffffu, rest, 1);
        rest += __shfl_xor_sync(0xffffffffu, rest, 2);
        if (ql == 0) g_rest[base + w8q] = rest;

        #pragma unroll
        for (int i = 0; i < 8; i++)
            x1p[i] = add2(x1p[i], shflxor2(x1p[i], 16));
        #pragma unroll
        for (int r = 0; r < 4; r++) {
            ull v = add2((rh == 0) ? x1p[r] : x1p[4 + r], blp);
            float lo, hi; upk2(v, lo, hi);
            g_x1[(size_t)(base + w8 + 2 * r)     * HID + lane] = lo;
            g_x1[(size_t)(base + w8 + 2 * r + 1) * HID + lane] = hi;
        }
    }
}

// ---- K2: register-tiled syrk S1/S2 (L1-cached, high-occupancy, MLP-8) ----
// 512 threads = 8 groups of 64; thread (ki,li) owns 4x4 tile. Per 4-row iter:
// 8 independent LDG.128 (L1-cached, group-shared lines) + 32 fma2.
__global__ __launch_bounds__(512) void stats_kernel(
        const float* __restrict__ g1, const float* __restrict__ be1,
        const float* __restrict__ Wl2, const float* __restrict__ bl2,
        const float* __restrict__ g2, const float* __restrict__ be2) {
    __shared__ float sred[8 * 1024];
    __shared__ float s1red[8 * 32];
    __shared__ int isLast;
    const int t = threadIdx.x;
    const int grp = t >> 6;                      // 0..7
    const int t6 = t & 63;
    const int ki = t6 >> 3, li = t6 & 7;
    const int g = blockIdx.x * 8 + grp;          // 2048 groups, 64 rows each
    const float* base = g_x1 + (size_t)g * 64 * HID;

    ull acc[8];
    #pragma unroll
    for (int i = 0; i < 8; i++) acc[i] = 0ull;
    float s1v[4] = {0.f, 0.f, 0.f, 0.f};

    #pragma unroll 1
    for (int r = 0; r < 64; r += 4) {
        float4 a[4], b[4];
        #pragma unroll
        for (int u = 0; u < 4; u++) {
            a[u] = __ldg((const float4*)(base + (size_t)(r + u) * HID + 4 * ki));
            b[u] = __ldg((const float4*)(base + (size_t)(r + u) * HID + 4 * li));
        }
        #pragma unroll
        for (int u = 0; u < 4; u++) {
            ull b01 = pk2(b[u].x, b[u].y), b23 = pk2(b[u].z, b[u].w);
            ull ax = pk2(a[u].x, a[u].x), ay = pk2(a[u].y, a[u].y);
            ull az = pk2(a[u].z, a[u].z), aw = pk2(a[u].w, a[u].w);
            acc[0] = fma2(ax, b01, acc[0]); acc[1] = fma2(ax, b23, acc[1]);
            acc[2] = fma2(ay, b01, acc[2]); acc[3] = fma2(ay, b23, acc[3]);
            acc[4] = fma2(az, b01, acc[4]); acc[5] = fma2(az, b23, acc[5]);
            acc[6] = fma2(aw, b01, acc[6]); acc[7] = fma2(aw, b23, acc[7]);
            if (li == 0) {
                s1v[0] += a[u].x; s1v[1] += a[u].y;
                s1v[2] += a[u].z; s1v[3] += a[u].w;
            }
        }
    }

    // stage group results, sum across the 8 groups, one atomic per element
    #pragma unroll
    for (int i = 0; i < 4; i++) {
        #pragma unroll
        for (int j = 0; j < 2; j++) {
            float lo, hi; upk2(acc[i * 2 + j], lo, hi);
            sred[grp * 1024 + (4 * ki + i) * 32 + 4 * li + 2 * j]     = lo;
            sred[grp * 1024 + (4 * ki + i) * 32 + 4 * li + 2 * j + 1] = hi;
        }
    }
    if (li == 0) {
        #pragma unroll
        for (int i = 0; i < 4; i++) s1red[grp * 32 + 4 * ki + i] = s1v[i];
    }
    __syncthreads();
    for (int i = t; i < 1024; i += 512) {
        float s = 0.f;
        #pragma unroll
        for (int w = 0; w < 8; w++) s += sred[w * 1024 + i];
        atomicAdd(&g_S2[i], s);
    }
    if (t < 32) {
        float s = 0.f;
        #pragma unroll
        for (int w = 0; w < 8; w++) s += s1red[w * 32 + t];
        atomicAdd(&g_S1[t], s);
    }
    __syncthreads();

    if (t == 0) {
        __threadfence();
        int old = atomicAdd(&g_cnt, 1);
        isLast = (old == (int)gridDim.x - 1) ? 1 : 0;
    }
    __syncthreads();
    if (!isLast) return;

    // ---- closed-form BN fold (512 threads; overlays sred) ----
    float* m1s = sred;            // 32
    float* a1s = sred + 32;       // 32
    float* a2s = sred + 64;       // 32
    float* qv  = sred + 96;       // 32*33
    float* Cm  = qv + 1056;       // 32*33
    float* part = Cm + 1056;      // 32*33
    const int j  = t & 31;
    const int kw = t >> 5;        // 0..15
    const float invN = 1.f / (float)NROWS;

    if (kw == 0) {
        float m1 = __ldcg(&g_S1[j]) * invN;
        float v1 = __ldcg(&g_S2[j * HID + j]) * invN - m1 * m1;
        m1s[j] = m1;
        a1s[j] = g1[j] * rsqrtf(v1 + EPSV);
    }
    __syncthreads();
    #pragma unroll
    for (int c = 0; c < 2; c++) {
        int kk = c * 16 + kw;
        Cm[kk * 33 + j] = __ldcg(&g_S2[kk * HID + j]) * invN - m1s[kk] * m1s[j];
        qv[kk * 33 + j] = a1s[kk] * Wl2[kk * HID + j];
    }
    __syncthreads();
    #pragma unroll
    for (int c = 0; c < 2; c++) {
        int kk = c * 16 + kw;
        float accv = 0.f;
        #pragma unroll 8
        for (int ll = 0; ll < HID; ll++) accv = fmaf(qv[ll * 33 + j], Cm[kk * 33 + ll], accv);
        part[kk * 33 + j] = qv[kk * 33 + j] * accv;
    }
    __syncthreads();

    if (kw == 0) {
        float vy = 0.f;
        #pragma unroll
        for (int m = 0; m < HID; m++) vy += part[m * 33 + j];
        float my = bl2[j];
        #pragma unroll
        for (int m = 0; m < HID; m++) my = fmaf(be1[m], Wl2[m * HID + j], my);
        float a2 = g2[j] * rsqrtf(vy + EPSV);
        a2s[j] = a2;
        float cpart = fmaf(a2, bl2[j] - my, be2[j]);
        __syncwarp();
        float wt = 0.f;
        #pragma unroll
        for (int jj = 0; jj < HID; jj++) wt = fmaf(Wl2[j * HID + jj], a2s[jj], wt);
        g_u[j] = a1s[j] * wt;
        cpart = fmaf(be1[j] - a1s[j] * m1s[j], wt, cpart);
        #pragma unroll
        for (int off = 16; off > 0; off >>= 1) cpart += __shfl_down_sync(0xffffffffu, cpart, off);
        if (j == 0) g_c0 = cpart;
    }
}

// ---- K3: out = rest + x1 . u + c0 (row-major x1 via smem tile) ----
__global__ __launch_bounds__(256) void out_kernel(float* __restrict__ out) {
    __shared__ float s[256 * 33];
    __shared__ float us[HID];
    __shared__ float c0s;
    const int t = threadIdx.x;
    const int base = blockIdx.x * 256;
    #pragma unroll
    for (int si = 0; si < 32; si++) {
        int i = t + si * 256;
        int r = i >> 5, jj = i & 31;
        s[r * 33 + jj] = g_x1[(size_t)base * HID + i];
    }
    if (t < HID) us[t] = g_u[t];
    if (t == HID) c0s = g_c0;
    __syncthreads();
    float acc = g_rest[base + t] + c0s;
    #pragma unroll 8
    for (int jj = 0; jj < HID; jj++)
        acc = fmaf(s[t * 33 + jj], us[jj], acc);
    out[base + t] = acc;
}

extern "C" void kernel_launch(void* const* d_in, const int* in_sizes, int n_in,
                              void* d_out, int out_size) {
    const float* Xi_dense  = (const float*)d_in[0];
    const int*   Xi_sparse = (const int*)d_in[1];
    const float* Xv   = (const float*)d_in[2];
    const float* bias = (const float*)d_in[3];
    const float* W1d  = (const float*)d_in[4];
    const float* b1d  = (const float*)d_in[5];
    const float* T1   = (const float*)d_in[6];
    const float* W2d  = (const float*)d_in[7];
    const float* b2d  = (const float*)d_in[8];
    const float* T2   = (const float*)d_in[9];
    const float* Wl1  = (const float*)d_in[10];
    const float* bl1  = (const float*)d_in[11];
    const float* g1   = (const float*)d_in[12];
    const float* be1  = (const float*)d_in[13];
    const float* Wl2  = (const float*)d_in[14];
    const float* bl2  = (const float*)d_in[15];
    const float* g2   = (const float*)d_in[16];
    const float* be2  = (const float*)d_in[17];
    float* out = (float*)d_out;

    size_t smem = (size_t)SMEM_WORDS * sizeof(float);
    cudaFuncSetAttribute(main_kernel, cudaFuncAttributeMaxDynamicSharedMemorySize, (int)smem);

    wprep_kernel<<<(NSPARSE * EMBD * 16 + 255) / 256, 256>>>(Wl1);
    rowsum_kernel<<<(NSPARSE * VOCABSZ * 4) / 256, 256>>>(T1);
    main_kernel<<<NROWS / 128, 256, smem>>>(Xi_dense, Xi_sparse, Xv, bias,
                                            T2, W1d, b1d, W2d, b2d, Wl1, bl1);
    stats_kernel<<<256, 512>>>(g1, be1, Wl2, bl2, g2, be2);
    out_kernel<<<NROWS / 256, 256>>>(out);
}

// round 17
// speedup vs baseline: 1.3778x; 1.0157x over previous
#include <cuda_runtime.h>
#include <cstdint>
#include <cstddef>

#define NROWS 131072
#define NDENSE 13
#define NSPARSE 26
#define NFIELD 39
#define EMBD 16
#define HID 32
#define VOCABSZ 100000
#define EPSV 1e-5f
#define DEPTH 4

// ---- scratch (static device globals; no allocation) ----
__device__ float g_x1[(size_t)NROWS * HID];   // ROW-major [NROWS][HID]
__device__ float g_rest[NROWS];
__device__ float g_R1[(size_t)NSPARSE * VOCABSZ];  // T1 row sums
typedef unsigned long long ull;
__device__ ull   g_Wp[NSPARSE * EMBD * 16];   // (w[e][cp], w[e][cp+16]) pairs
__device__ float g_S1[HID];
__device__ float g_S2[HID * HID];
__device__ float g_u[HID];
__device__ float g_c0;
__device__ int   g_cnt;

// ---- packed f32x2 helpers (Blackwell) ----
__device__ __forceinline__ ull pk2(float a, float b) {
    ull r;
    asm("mov.b64 %0, {%1, %2};" : "=l"(r)
        : "r"(__float_as_uint(a)), "r"(__float_as_uint(b)));
    return r;
}
__device__ __forceinline__ void upk2(ull v, float& a, float& b) {
    unsigned int x, y;
    asm("mov.b64 {%0, %1}, %2;" : "=r"(x), "=r"(y) : "l"(v));
    a = __uint_as_float(x); b = __uint_as_float(y);
}
__device__ __forceinline__ ull fma2(ull a, ull b, ull c) {
    ull d;
    asm("fma.rn.f32x2 %0, %1, %2, %3;" : "=l"(d) : "l"(a), "l"(b), "l"(c));
    return d;
}
__device__ __forceinline__ ull add2(ull a, ull b) {
    ull d;
    asm("add.rn.f32x2 %0, %1, %2;" : "=l"(d) : "l"(a), "l"(b));
    return d;
}
__device__ __forceinline__ ull mul2(ull a, ull b) {
    ull d;
    asm("mul.rn.f32x2 %0, %1, %2;" : "=l"(d) : "l"(a), "l"(b));
    return d;
}
__device__ __forceinline__ ull shflxor2(ull v, int m) {
    unsigned int x = (unsigned int)v, y = (unsigned int)(v >> 32);
    x = __shfl_xor_sync(0xffffffffu, x, m);
    y = __shfl_xor_sync(0xffffffffu, y, m);
    return (ull)x | ((ull)y << 32);
}
__device__ __forceinline__ uint32_t smem_u32(const void* p) {
    uint32_t a;
    asm("{ .reg .u64 t; cvta.to.shared.u64 t, %1; cvt.u32.u64 %0, t; }"
        : "=r"(a) : "l"(p));
    return a;
}
__device__ __forceinline__ void cpasync16(uint32_t dst, const void* src) {
    asm volatile("cp.async.cg.shared.global [%0], [%1], 16;" :: "r"(dst), "l"(src));
}
#define CP_COMMIT() asm volatile("cp.async.commit_group;" ::: "memory")
#define CP_WAIT(n)  asm volatile("cp.async.wait_group %0;" :: "n"(n) : "memory")

// smem word offsets (floats)
#define OFF_RING  0                           // 8 warps * DEPTH * 128 = 4096
#define OFF_ST    (OFF_RING + 8 * DEPTH * 128)
#define OFF_A2P   (OFF_ST + 8 * 160)          // 13*64 packed replicated pairs
#define OFF_B2P   (OFF_A2P + NDENSE * 64)
#define OFF_W2    (OFF_B2P + NDENSE * 64)
#define OFF_BB2   (OFF_W2 + NDENSE * EMBD)
#define OFF_XDT   (OFF_BB2 + NDENSE * EMBD)   // dense xi transposed [13][66]
#define OFF_XVDT  (OFF_XDT + NDENSE * 66)
#define OFF_XST   (OFF_XVDT + NDENSE * 66)    // sparse idx transposed [26][65]
#define OFF_XVST  (OFF_XST + NSPARSE * 65)
#define OFF_W1S   (OFF_XVST + NSPARSE * 65)
#define OFF_B1S   (OFF_W1S + 16)
#define OFF_BIAS  (OFF_B1S + 16)
#define SMEM_WORDS (OFF_BIAS + 64)

// ---- K0a: T1 row-sums (streaming). Quad per row. ----
__global__ __launch_bounds__(256) void rowsum_kernel(const float* __restrict__ T1) {
    int t = blockIdx.x * 256 + threadIdx.x;
    int row = t >> 2, part = t & 3;
    float4 v = __ldcs((const float4*)(T1 + (size_t)row * EMBD + part * 4));
    float s = (v.x + v.y) + (v.z + v.w);
    s += __shfl_xor_sync(0xffffffffu, s, 1);
    s += __shfl_xor_sync(0xffffffffu, s, 2);
    if (part == 0) g_R1[row] = s;
}

// ---- K0b: Wl1 sparse-row pair table ----
__global__ __launch_bounds__(256) void wprep_kernel(const float* __restrict__ Wl1) {
    int i = blockIdx.x * 256 + threadIdx.x;
    if (i < NSPARSE * EMBD * 16) {
        int row = i >> 4, cp = i & 15;
        const float* wr = Wl1 + (size_t)(NDENSE * EMBD + row) * HID;
        g_Wp[i] = pk2(wr[cp], wr[cp + 16]);
    }
}

// ---- K1: fused embed + FM + deep@Wl1 (round-16 body, best measured) ----
__global__ __launch_bounds__(256, 3) void main_kernel(
    const float* __restrict__ Xi_dense, const int* __restrict__ Xi_sparse,
    const float* __restrict__ Xv, const float* __restrict__ bias,
    const float* __restrict__ T2,
    const float* __restrict__ W1d, const float* __restrict__ b1d,
    const float* __restrict__ W2d, const float* __restrict__ b2d,
    const float* __restrict__ Wl1, const float* __restrict__ bl1)
{
    extern __shared__ float sm[];
    float* sst   = sm + OFF_ST;
    float* sA2p  = sm + OFF_A2P;
    float* sB2p  = sm + OFF_B2P;
    float* sW2   = sm + OFF_W2;
    float* sbb2  = sm + OFF_BB2;
    float* sXdT  = sm + OFF_XDT;
    float* sXvDT = sm + OFF_XVDT;
    int*   sXsT  = (int*)(sm + OFF_XST);
    float* sXvST = sm + OFF_XVST;
    float* sw1   = sm + OFF_W1S;
    float* sb1   = sm + OFF_B1S;
    float* sBias = sm + OFF_BIAS;

    const int tid = threadIdx.x;

    for (int i = tid; i < NDENSE * 16; i += 256) {
        int f = i >> 4, cp = i & 15;
        float a0 = 0.f, a1 = 0.f, b0 = 0.f, b1 = 0.f;
        #pragma unroll
        for (int e = 0; e < EMBD; e++) {
            float w0 = Wl1[(f * EMBD + e) * HID + cp];
            float w1 = Wl1[(f * EMBD + e) * HID + cp + 16];
            float ww = W2d[f * EMBD + e], bb = b2d[f * EMBD + e];
            a0 = fmaf(ww, w0, a0); a1 = fmaf(ww, w1, a1);
            b0 = fmaf(bb, w0, b0); b1 = fmaf(bb, w1, b1);
        }
        sA2p[f * 64 + cp * 4 + 0] = a0; sA2p[f * 64 + cp * 4 + 1] = a0;
        sA2p[f * 64 + cp * 4 + 2] = a1; sA2p[f * 64 + cp * 4 + 3] = a1;
        sB2p[f * 64 + cp * 4 + 0] = b0; sB2p[f * 64 + cp * 4 + 1] = b0;
        sB2p[f * 64 + cp * 4 + 2] = b1; sB2p[f * 64 + cp * 4 + 3] = b1;
    }
    if (tid < NDENSE * EMBD) {
        sW2[tid]  = W2d[tid];
        sbb2[tid] = b2d[tid];
    }
    if (tid < NDENSE) {
        float a = 0.f, b = 0.f;
        #pragma unroll
        for (int e = 0; e < EMBD; e++) {
            a += W1d[tid * EMBD + e];
            b += b1d[tid * EMBD + e];
        }
        sw1[tid] = a; sb1[tid] = b;
    }
    if (blockIdx.x == 0) {
        if (tid < HID) g_S1[tid] = 0.f;
        for (int i = tid; i < HID * HID; i += 256) g_S2[i] = 0.f;
        if (tid == 0) g_cnt = 0;
    }

    const int warp = tid >> 5;
    const int lane = tid & 31;
    const int q    = lane >> 2;
    const int ql   = lane & 3;
    const int rh   = lane >> 4;
    const int cp   = lane & 15;
    const int w8   = warp * 8;
    const int w8q  = w8 + q;
    const float blj = __ldg(bl1 + lane);
    const ull blp = pk2(blj, blj);
    const ull* wlane = g_Wp + rh * 16 + cp;
    float* stw = sst + warp * 160;
    const uint32_t ringb = smem_u32(sm) + (uint32_t)(OFF_RING + warp * (DEPTH * 128)) * 4u;
    const uint32_t laneoff = (uint32_t)(q * 4 + ql) * 16u;
    const float* ringw = sm + OFF_RING + warp * (DEPTH * 128);

    #pragma unroll 1
    for (int g = 0; g < 2; g++) {
        const int base = blockIdx.x * 128 + g * 64;
        __syncthreads();
        for (int i = tid; i < 64 * NSPARSE; i += 256) {
            int r = i / NSPARSE, f = i % NSPARSE;
            sXsT[f * 65 + r] = Xi_sparse[(size_t)base * NSPARSE + i];
        }
        for (int i = tid; i < 64 * NFIELD; i += 256) {
            int r = i / NFIELD, f = i % NFIELD;
            float val = Xv[(size_t)base * NFIELD + i];
            if (f < NDENSE) sXvDT[f * 66 + r] = val;
            else            sXvST[(f - NDENSE) * 65 + r] = val;
        }
        for (int i = tid; i < 64 * NDENSE; i += 256) {
            int r = i / NDENSE, f = i % NDENSE;
            sXdT[f * 66 + r] = Xi_dense[(size_t)base * NDENSE + i];
        }
        if (tid < 64) sBias[tid] = bias[base + tid];
        __syncthreads();

        ull x1p[8];
        #pragma unroll
        for (int i = 0; i < 8; i++) x1p[i] = 0ull;
        ull s01 = 0ull, s23 = 0ull, sqp = 0ull;
        float rest = (ql == 0) ? sBias[w8q] : 0.f;

        #pragma unroll
        for (int f = 0; f < NDENSE; f++) {
            float xi = sXdT[f * 66 + w8q];
            float v  = sXvDT[f * 66 + w8q];
            if (ql == 0) rest = fmaf(v, fmaf(xi, sw1[f], sb1[f]), rest);
            float4 w2 = *(const float4*)(sW2 + f * EMBD + ql * 4);
            float4 c2 = *(const float4*)(sbb2 + f * EMBD + ql * 4);
            float t0 = fmaf(xi, w2.x, c2.x) * v;
            float t1 = fmaf(xi, w2.y, c2.y) * v;
            float t2 = fmaf(xi, w2.z, c2.z) * v;
            float t3 = fmaf(xi, w2.w, c2.w) * v;
            ull p01 = pk2(t0, t1), p23 = pk2(t2, t3);
            s01 = add2(s01, p01); s23 = add2(s23, p23);
            sqp = fma2(p01, p01, sqp); sqp = fma2(p23, p23, sqp);
            if ((f & 1) == rh) {
                ulonglong2 ap = *(const ulonglong2*)(sA2p + f * 64 + cp * 4);
                ulonglong2 bp = *(const ulonglong2*)(sB2p + f * 64 + cp * 4);
                #pragma unroll
                for (int r = 0; r < 4; r++) {
                    ull xi2 = *(const ull*)(sXdT + f * 66 + w8 + 2 * r);
                    ull v2  = *(const ull*)(sXvDT + f * 66 + w8 + 2 * r);
                    ull xiv2 = mul2(xi2, v2);
                    x1p[r]     = fma2(xiv2, ap.x, x1p[r]);
                    x1p[r]     = fma2(v2,   bp.x, x1p[r]);
                    x1p[4 + r] = fma2(xiv2, ap.y, x1p[4 + r]);
                    x1p[4 + r] = fma2(v2,   bp.y, x1p[4 + r]);
                }
            }
        }

        #pragma unroll
        for (int pf = 0; pf < DEPTH; pf++) {
            int id = sXsT[pf * 65 + w8 + q];
            const float* src = T2 + ((size_t)pf * VOCABSZ + (size_t)id) * EMBD + ql * 4;
            cpasync16(ringb + (uint32_t)(pf & (DEPTH - 1)) * 512u + laneoff, src);
            CP_COMMIT();
        }
        float rs0 = __ldcg(g_R1 + sXsT[w8q]);
        float rs1 = __ldcg(g_R1 + VOCABSZ + sXsT[65 + w8q]);

        #pragma unroll 1
        for (int f = 0; f < NSPARSE; f++) {
            CP_WAIT(DEPTH - 1);
            float4 cb = *(const float4*)(ringw + (f & (DEPTH - 1)) * 128 + (q * 4 + ql) * 4);
            float cv = sXvST[f * 65 + w8q];
            if (ql == 0) rest = fmaf(cv, rs0, rest);
            rs0 = rs1;
            if (f + 2 < NSPARSE)
                rs1 = __ldcg(g_R1 + (size_t)(f + 2) * VOCABSZ + sXsT[(f + 2) * 65 + w8q]);

            float t0 = cb.x * cv, t1 = cb.y * cv, t2 = cb.z * cv, t3 = cb.w * cv;
            ull p01 = pk2(t0, t1), p23 = pk2(t2, t3);
            s01 = add2(s01, p01); s23 = add2(s23, p23);
            sqp = fma2(p01, p01, sqp); sqp = fma2(p23, p23, sqp);

            stw[(2 * ql + 0) * 20 + 0 + q] = t0;
            stw[(2 * ql + 0) * 20 + 8 + q] = t1;
            stw[(2 * ql + 1) * 20 + 0 + q] = t2;
            stw[(2 * ql + 1) * 20 + 8 + q] = t3;
            __syncwarp();

            #pragma unroll
            for (int p = 0; p < 8; p++) {
                ull wp = __ldg(wlane + (f * 16 + 2 * p) * 16);
                float wlo, whi; upk2(wp, wlo, whi);
                ull w0 = pk2(wlo, wlo), w1 = pk2(whi, whi);
                const ulonglong2* tp = (const ulonglong2*)(stw + p * 20 + rh * 8);
                ulonglong2 ta = tp[0];
                ulonglong2 tb = tp[1];
                x1p[0] = fma2(ta.x, w0, x1p[0]);
                x1p[1] = fma2(ta.y, w0, x1p[1]);
                x1p[2] = fma2(tb.x, w0, x1p[2]);
                x1p[3] = fma2(tb.y, w0, x1p[3]);
                x1p[4] = fma2(ta.x, w1, x1p[4]);
                x1p[5] = fma2(ta.y, w1, x1p[5]);
                x1p[6] = fma2(tb.x, w1, x1p[6]);
                x1p[7] = fma2(tb.y, w1, x1p[7]);
            }
            __syncwarp();

            {
                int pf = f + DEPTH;
                if (pf < NSPARSE) {
                    int id = sXsT[pf * 65 + w8 + q];
                    const float* src = T2 + ((size_t)pf * VOCABSZ + (size_t)id) * EMBD + ql * 4;
                    cpasync16(ringb + (uint32_t)(pf & (DEPTH - 1)) * 512u + laneoff, src);
                }
                CP_COMMIT();
            }
        }

        {
            ull f2 = fma2(s01, s01, 0ull);
            f2 = fma2(s23, s23, f2);
            float flo, fhi; upk2(f2, flo, fhi);
            float qlo, qhi; upk2(sqp, qlo, qhi);
            rest += 0.5f * ((flo + fhi) - (qlo + qhi));
        }
        rest += __shfl_xor_sync(0xffffffffu, rest, 1);
        rest += __shfl_xor_sync(0xffffffffu, rest, 2);
        if (ql == 0) g_rest[base + w8q] = rest;

        #pragma unroll
        for (int i = 0; i < 8; i++)
            x1p[i] = add2(x1p[i], shflxor2(x1p[i], 16));
        #pragma unroll
        for (int r = 0; r < 4; r++) {
            ull v = add2((rh == 0) ? x1p[r] : x1p[4 + r], blp);
            float lo, hi; upk2(v, lo, hi);
            g_x1[(size_t)(base + w8 + 2 * r)     * HID + lane] = lo;
            g_x1[(size_t)(base + w8 + 2 * r + 1) * HID + lane] = hi;
        }
    }
}

// ---- K2: register-tiled syrk S1/S2, software-pipelined 2-row double buffer ----
// 512 blocks x 256 threads = 2048 groups of 64 rows, single wave, ~32 warps/SM.
// Thread (ki,li) owns 4x4 tile; loads for rows r+2 issue before computing r.
__global__ __launch_bounds__(256) void stats_kernel(
        const float* __restrict__ g1, const float* __restrict__ be1,
        const float* __restrict__ Wl2, const float* __restrict__ bl2,
        const float* __restrict__ g2, const float* __restrict__ be2) {
    __shared__ float sred[4 * 1024];
    __shared__ float s1red[4 * 32];
    __shared__ int isLast;
    const int t = threadIdx.x;
    const int grp = t >> 6;                      // 0..3
    const int t6 = t & 63;
    const int ki = t6 >> 3, li = t6 & 7;
    const int g = blockIdx.x * 4 + grp;          // 2048 groups, 64 rows each
    const float* base = g_x1 + (size_t)g * 64 * HID;

    ull acc[8];
    #pragma unroll
    for (int i = 0; i < 8; i++) acc[i] = 0ull;
    float s1v[4] = {0.f, 0.f, 0.f, 0.f};

    float4 ca0 = __ldg((const float4*)(base + 4 * ki));
    float4 cb0 = __ldg((const float4*)(base + 4 * li));
    float4 ca1 = __ldg((const float4*)(base + HID + 4 * ki));
    float4 cb1 = __ldg((const float4*)(base + HID + 4 * li));

    #pragma unroll 1
    for (int r = 0; r < 64; r += 2) {
        float4 na0, nb0, na1, nb1;
        if (r + 2 < 64) {
            na0 = __ldg((const float4*)(base + (size_t)(r + 2) * HID + 4 * ki));
            nb0 = __ldg((const float4*)(base + (size_t)(r + 2) * HID + 4 * li));
            na1 = __ldg((const float4*)(base + (size_t)(r + 3) * HID + 4 * ki));
            nb1 = __ldg((const float4*)(base + (size_t)(r + 3) * HID + 4 * li));
        }
        {
            ull b01 = pk2(cb0.x, cb0.y), b23 = pk2(cb0.z, cb0.w);
            ull ax = pk2(ca0.x, ca0.x), ay = pk2(ca0.y, ca0.y);
            ull az = pk2(ca0.z, ca0.z), aw = pk2(ca0.w, ca0.w);
            acc[0] = fma2(ax, b01, acc[0]); acc[1] = fma2(ax, b23, acc[1]);
            acc[2] = fma2(ay, b01, acc[2]); acc[3] = fma2(ay, b23, acc[3]);
            acc[4] = fma2(az, b01, acc[4]); acc[5] = fma2(az, b23, acc[5]);
            acc[6] = fma2(aw, b01, acc[6]); acc[7] = fma2(aw, b23, acc[7]);
        }
        {
            ull b01 = pk2(cb1.x, cb1.y), b23 = pk2(cb1.z, cb1.w);
            ull ax = pk2(ca1.x, ca1.x), ay = pk2(ca1.y, ca1.y);
            ull az = pk2(ca1.z, ca1.z), aw = pk2(ca1.w, ca1.w);
            acc[0] = fma2(ax, b01, acc[0]); acc[1] = fma2(ax, b23, acc[1]);
            acc[2] = fma2(ay, b01, acc[2]); acc[3] = fma2(ay, b23, acc[3]);
            acc[4] = fma2(az, b01, acc[4]); acc[5] = fma2(az, b23, acc[5]);
            acc[6] = fma2(aw, b01, acc[6]); acc[7] = fma2(aw, b23, acc[7]);
        }
        if (li == 0) {
            s1v[0] += ca0.x + ca1.x;
            s1v[1] += ca0.y + ca1.y;
            s1v[2] += ca0.z + ca1.z;
            s1v[3] += ca0.w + ca1.w;
        }
        ca0 = na0; cb0 = nb0; ca1 = na1; cb1 = nb1;
    }

    // stage group results, sum across the 4 groups, one atomic per element
    #pragma unroll
    for (int i = 0; i < 4; i++) {
        #pragma unroll
        for (int j = 0; j < 2; j++) {
            float lo, hi; upk2(acc[i * 2 + j], lo, hi);
            sred[grp * 1024 + (4 * ki + i) * 32 + 4 * li + 2 * j]     = lo;
            sred[grp * 1024 + (4 * ki + i) * 32 + 4 * li + 2 * j + 1] = hi;
        }
    }
    if (li == 0) {
        #pragma unroll
        for (int i = 0; i < 4; i++) s1red[grp * 32 + 4 * ki + i] = s1v[i];
    }
    __syncthreads();
    for (int i = t; i < 1024; i += 256) {
        float s = (sred[i] + sred[1024 + i]) + (sred[2048 + i] + sred[3072 + i]);
        atomicAdd(&g_S2[i], s);
    }
    if (t < 32) {
        float s = (s1red[t] + s1red[32 + t]) + (s1red[64 + t] + s1red[96 + t]);
        atomicAdd(&g_S1[t], s);
    }
    __syncthreads();

    if (t == 0) {
        __threadfence();
        int old = atomicAdd(&g_cnt, 1);
        isLast = (old == (int)gridDim.x - 1) ? 1 : 0;
    }
    __syncthreads();
    if (!isLast) return;

    // ---- closed-form BN fold (256 threads; overlays sred) ----
    float* m1s = sred;            // 32
    float* a1s = sred + 32;       // 32
    float* a2s = sred + 64;       // 32
    float* qv  = sred + 96;       // 32*33
    float* Cm  = qv + 1056;       // 32*33
    float* part = Cm + 1056;      // 32*33
    const int j  = t & 31;
    const int kw = t >> 5;        // 0..7
    const float invN = 1.f / (float)NROWS;

    if (kw == 0) {
        float m1 = __ldcg(&g_S1[j]) * invN;
        float v1 = __ldcg(&g_S2[j * HID + j]) * invN - m1 * m1;
        m1s[j] = m1;
        a1s[j] = g1[j] * rsqrtf(v1 + EPSV);
    }
    __syncthreads();
    #pragma unroll
    for (int c = 0; c < 4; c++) {
        int kk = c * 8 + kw;
        Cm[kk * 33 + j] = __ldcg(&g_S2[kk * HID + j]) * invN - m1s[kk] * m1s[j];
        qv[kk * 33 + j] = a1s[kk] * Wl2[kk * HID + j];
    }
    __syncthreads();
    #pragma unroll
    for (int c = 0; c < 4; c++) {
        int kk = c * 8 + kw;
        float accv = 0.f;
        #pragma unroll 8
        for (int ll = 0; ll < HID; ll++) accv = fmaf(qv[ll * 33 + j], Cm[kk * 33 + ll], accv);
        part[kk * 33 + j] = qv[kk * 33 + j] * accv;
    }
    __syncthreads();

    if (kw == 0) {
        float vy = 0.f;
        #pragma unroll
        for (int m = 0; m < HID; m++) vy += part[m * 33 + j];
        float my = bl2[j];
        #pragma unroll
        for (int m = 0; m < HID; m++) my = fmaf(be1[m], Wl2[m * HID + j], my);
        float a2 = g2[j] * rsqrtf(vy + EPSV);
        a2s[j] = a2;
        float cpart = fmaf(a2, bl2[j] - my, be2[j]);
        __syncwarp();
        float wt = 0.f;
        #pragma unroll
        for (int jj = 0; jj < HID; jj++) wt = fmaf(Wl2[j * HID + jj], a2s[jj], wt);
        g_u[j] = a1s[j] * wt;
        cpart = fmaf(be1[j] - a1s[j] * m1s[j], wt, cpart);
        #pragma unroll
        for (int off = 16; off > 0; off >>= 1) cpart += __shfl_down_sync(0xffffffffu, cpart, off);
        if (j == 0) g_c0 = cpart;
    }
}

// ---- K3: out = rest + x1 . u + c0 (row-major x1 via smem tile) ----
__global__ __launch_bounds__(256) void out_kernel(float* __restrict__ out) {
    __shared__ float s[256 * 33];
    __shared__ float us[HID];
    __shared__ float c0s;
    const int t = threadIdx.x;
    const int base = blockIdx.x * 256;
    #pragma unroll
    for (int si = 0; si < 32; si++) {
        int i = t + si * 256;
        int r = i >> 5, jj = i & 31;
        s[r * 33 + jj] = g_x1[(size_t)base * HID + i];
    }
    if (t < HID) us[t] = g_u[t];
    if (t == HID) c0s = g_c0;
    __syncthreads();
    float acc = g_rest[base + t] + c0s;
    #pragma unroll 8
    for (int jj = 0; jj < HID; jj++)
        acc = fmaf(s[t * 33 + jj], us[jj], acc);
    out[base + t] = acc;
}

extern "C" void kernel_launch(void* const* d_in, const int* in_sizes, int n_in,
                              void* d_out, int out_size) {
    const float* Xi_dense  = (const float*)d_in[0];
    const int*   Xi_sparse = (const int*)d_in[1];
    const float* Xv   = (const float*)d_in[2];
    const float* bias = (const float*)d_in[3];
    const float* W1d  = (const float*)d_in[4];
    const float* b1d  = (const float*)d_in[5];
    const float* T1   = (const float*)d_in[6];
    const float* W2d  = (const float*)d_in[7];
    const float* b2d  = (const float*)d_in[8];
    const float* T2   = (const float*)d_in[9];
    const float* Wl1  = (const float*)d_in[10];
    const float* bl1  = (const float*)d_in[11];
    const float* g1   = (const float*)d_in[12];
    const float* be1  = (const float*)d_in[13];
    const float* Wl2  = (const float*)d_in[14];
    const float* bl2  = (const float*)d_in[15];
    const float* g2   = (const float*)d_in[16];
    const float* be2  = (const float*)d_in[17];
    float* out = (float*)d_out;

    size_t smem = (size_t)SMEM_WORDS * sizeof(float);
    cudaFuncSetAttribute(main_kernel, cudaFuncAttributeMaxDynamicSharedMemorySize, (int)smem);

    wprep_kernel<<<(NSPARSE * EMBD * 16 + 255) / 256, 256>>>(Wl1);
    rowsum_kernel<<<(NSPARSE * VOCABSZ * 4) / 256, 256>>>(T1);
    main_kernel<<<NROWS / 128, 256, smem>>>(Xi_dense, Xi_sparse, Xv, bias,
                                            T2, W1d, b1d, W2d, b2d, Wl1, bl1);
    stats_kernel<<<512, 256>>>(g1, be1, Wl2, bl2, g2, be2);
    out_kernel<<<NROWS / 256, 256>>>(out);
}